// round 10
// baseline (speedup 1.0000x reference)
#include <cuda_runtime.h>
#include <cuda_fp16.h>

// y = irfft2(rfft2(pad(u)) * rfft2(pad(k)), ortho) cropped.
// (4,64,251,509) fp32 -> 256 images 251x509, pad to 256x512.
// Pack z = u + i*k; with Z2 = FFT2(z):
//   P = U2*K2 = -0.25i*(Z2[ky,kx]^2 - conj(Z2[-ky,-kx])^2)
// conj(Z2[-ky,-kx]) = FFT_col(conj(Z[h,-kx])) -- conj-on-load, no gather.
// Combined ortho scale 2^-25.5 folded into the product.
// fp16 intermediates (tol 1e-3): g_Zh raw, g_Ph pre-scaled 2^6, T2 2^12.
// Stage2 dft16s are in-place DIF/DIT (bit-reversal = compile-time renaming)
// to cut register pressure -> 3 blocks/SM. Stage3 pairs 2 rows per IFFT.

#define IMGS 256
#define HH   251
#define WW   509
#define NJ   257
#define ZP   516   // half2 row stride of Z scratch
#define WPAD 260   // half2 row stride of product scratch
#define EX1S 10    // fft512 exchange-1 stride (16B aligned, conflict-free)
#define P512B 66   // fft512 exchange-2 stride (conflict-free both sides)
#define SROW 656   // smem float2 for fft512 (>= 64*10)
#define E2S  18    // fft256 exchange per-thread stride (float2)
#define E2C  288   // fft256 exchange per-column stride (float2) = 16*18

__device__ __half2 g_Zh[IMGS * HH * ZP];   // packed row spectra (fp16)
__device__ __half2 g_Ph[IMGS * HH * WPAD]; // product half-spectrum (fp16, x64)
__device__ float2  g_tw[512];              // tw[r] = exp(-2*pi*i*r/512)

__global__ void init_tw_kernel() {
    int r = threadIdx.x;
    double ang = -2.0 * 3.141592653589793238462643383279502884 * (double)r / 512.0;
    g_tw[r] = make_float2((float)cos(ang), (float)sin(ang));
}

__device__ __forceinline__ float2 cmul(float2 a, float2 b) {
    return make_float2(a.x*b.x - a.y*b.y, a.x*b.y + a.y*b.x);
}
__device__ __forceinline__ float2 cadd(float2 a, float2 b) { return make_float2(a.x+b.x, a.y+b.y); }
__device__ __forceinline__ float2 csub(float2 a, float2 b) { return make_float2(a.x-b.x, a.y-b.y); }
template<int DIR>
__device__ __forceinline__ float2 mulmi(float2 v) {   // * (-i) fwd, * (+i) inv
    return (DIR == 1) ? make_float2(v.y, -v.x) : make_float2(-v.y, v.x);
}

// bit-reverse of 4 bits (involution)
__device__ __constant__ const int BR16[16] =
    {0,8,4,12,2,10,6,14,1,9,5,13,3,11,7,15};

template<int DIR>
__device__ __forceinline__ void dft8(float2 x[8]) {
    const float C = 0.70710678118654752f;
    float2 t0 = cadd(x[0], x[4]), t4 = csub(x[0], x[4]);
    float2 t1 = cadd(x[1], x[5]), t5 = csub(x[1], x[5]);
    float2 t2 = cadd(x[2], x[6]), t6 = csub(x[2], x[6]);
    float2 t3 = cadd(x[3], x[7]), t7 = csub(x[3], x[7]);
    t5 = cmul(t5, make_float2(C, -DIR * C));
    t6 = mulmi<DIR>(t6);
    t7 = cmul(t7, make_float2(-C, -DIR * C));
    float2 p0 = cadd(t0, t2), q0 = csub(t0, t2);
    float2 p1 = cadd(t1, t3), q1 = mulmi<DIR>(csub(t1, t3));
    x[0] = cadd(p0, p1); x[4] = csub(p0, p1);
    x[2] = cadd(q0, q1); x[6] = csub(q0, q1);
    float2 r0 = cadd(t4, t6), s0 = csub(t4, t6);
    float2 r1 = cadd(t5, t7), s1 = mulmi<DIR>(csub(t5, t7));
    x[1] = cadd(r0, r1); x[5] = csub(r0, r1);
    x[3] = cadd(s0, s1); x[7] = csub(s0, s1);
}

// In-place DIF radix-2 DFT-16: natural input, output x[p] = X[BR16[p]].
template<int DIR>
__device__ __forceinline__ void dif16(float2 x[16]) {
    const float c1 = 0.92387953251128674f, s1 = 0.38268343236508978f;
    const float C = 0.70710678118654752f;
    const float2 W1 = make_float2(c1, -DIR*s1);
    const float2 W2 = make_float2(C,  -DIR*C);
    const float2 W3 = make_float2(s1, -DIR*c1);
    const float2 W5 = make_float2(-s1,-DIR*c1);
    const float2 W6 = make_float2(-C, -DIR*C);
    const float2 W7 = make_float2(-c1,-DIR*s1);
    float2 a, d;
    // half = 8, twiddles W16^j
    a=x[0]; d=csub(a,x[8]);  x[0]=cadd(a,x[8]);  x[8]=d;
    a=x[1]; d=csub(a,x[9]);  x[1]=cadd(a,x[9]);  x[9]=cmul(d,W1);
    a=x[2]; d=csub(a,x[10]); x[2]=cadd(a,x[10]); x[10]=cmul(d,W2);
    a=x[3]; d=csub(a,x[11]); x[3]=cadd(a,x[11]); x[11]=cmul(d,W3);
    a=x[4]; d=csub(a,x[12]); x[4]=cadd(a,x[12]); x[12]=mulmi<DIR>(d);
    a=x[5]; d=csub(a,x[13]); x[5]=cadd(a,x[13]); x[13]=cmul(d,W5);
    a=x[6]; d=csub(a,x[14]); x[6]=cadd(a,x[14]); x[14]=cmul(d,W6);
    a=x[7]; d=csub(a,x[15]); x[7]=cadd(a,x[15]); x[15]=cmul(d,W7);
    // half = 4, twiddles W8^j = {1, W2, -i, W6}
#pragma unroll
    for (int b0 = 0; b0 < 16; b0 += 8) {
        a=x[b0+0]; d=csub(a,x[b0+4]); x[b0+0]=cadd(a,x[b0+4]); x[b0+4]=d;
        a=x[b0+1]; d=csub(a,x[b0+5]); x[b0+1]=cadd(a,x[b0+5]); x[b0+5]=cmul(d,W2);
        a=x[b0+2]; d=csub(a,x[b0+6]); x[b0+2]=cadd(a,x[b0+6]); x[b0+6]=mulmi<DIR>(d);
        a=x[b0+3]; d=csub(a,x[b0+7]); x[b0+3]=cadd(a,x[b0+7]); x[b0+7]=cmul(d,W6);
    }
    // half = 2, twiddles {1, -i}
#pragma unroll
    for (int b0 = 0; b0 < 16; b0 += 4) {
        a=x[b0+0]; d=csub(a,x[b0+2]); x[b0+0]=cadd(a,x[b0+2]); x[b0+2]=d;
        a=x[b0+1]; d=csub(a,x[b0+3]); x[b0+1]=cadd(a,x[b0+3]); x[b0+3]=mulmi<DIR>(d);
    }
    // half = 1
#pragma unroll
    for (int b0 = 0; b0 < 16; b0 += 2) {
        a=x[b0]; float2 b=x[b0+1];
        x[b0]=cadd(a,b); x[b0+1]=csub(a,b);
    }
}

// In-place DIT radix-2 DFT-16: input x[p] = data[BR16[p]], natural output.
template<int DIR>
__device__ __forceinline__ void dit16(float2 x[16]) {
    const float c1 = 0.92387953251128674f, s1 = 0.38268343236508978f;
    const float C = 0.70710678118654752f;
    const float2 W1 = make_float2(c1, -DIR*s1);
    const float2 W2 = make_float2(C,  -DIR*C);
    const float2 W3 = make_float2(s1, -DIR*c1);
    const float2 W5 = make_float2(-s1,-DIR*c1);
    const float2 W6 = make_float2(-C, -DIR*C);
    const float2 W7 = make_float2(-c1,-DIR*s1);
    float2 a, b;
    // half = 1
#pragma unroll
    for (int b0 = 0; b0 < 16; b0 += 2) {
        a=x[b0]; b=x[b0+1];
        x[b0]=cadd(a,b); x[b0+1]=csub(a,b);
    }
    // half = 2, twiddles {1, -i}
#pragma unroll
    for (int b0 = 0; b0 < 16; b0 += 4) {
        a=x[b0+0]; b=x[b0+2];            x[b0+0]=cadd(a,b); x[b0+2]=csub(a,b);
        a=x[b0+1]; b=mulmi<DIR>(x[b0+3]); x[b0+1]=cadd(a,b); x[b0+3]=csub(a,b);
    }
    // half = 4, twiddles {1, W2, -i, W6}
#pragma unroll
    for (int b0 = 0; b0 < 16; b0 += 8) {
        a=x[b0+0]; b=x[b0+4];             x[b0+0]=cadd(a,b); x[b0+4]=csub(a,b);
        a=x[b0+1]; b=cmul(x[b0+5],W2);    x[b0+1]=cadd(a,b); x[b0+5]=csub(a,b);
        a=x[b0+2]; b=mulmi<DIR>(x[b0+6]); x[b0+2]=cadd(a,b); x[b0+6]=csub(a,b);
        a=x[b0+3]; b=cmul(x[b0+7],W6);    x[b0+3]=cadd(a,b); x[b0+7]=csub(a,b);
    }
    // half = 8, twiddles W16^j
    a=x[0]; b=x[8];            x[0]=cadd(a,b); x[8]=csub(a,b);
    a=x[1]; b=cmul(x[9],W1);   x[1]=cadd(a,b); x[9]=csub(a,b);
    a=x[2]; b=cmul(x[10],W2);  x[2]=cadd(a,b); x[10]=csub(a,b);
    a=x[3]; b=cmul(x[11],W3);  x[3]=cadd(a,b); x[11]=csub(a,b);
    a=x[4]; b=mulmi<DIR>(x[12]); x[4]=cadd(a,b); x[12]=csub(a,b);
    a=x[5]; b=cmul(x[13],W5);  x[5]=cadd(a,b); x[13]=csub(a,b);
    a=x[6]; b=cmul(x[14],W6);  x[6]=cadd(a,b); x[14]=csub(a,b);
    a=x[7]; b=cmul(x[15],W7);  x[7]=cadd(a,b); x[15]=csub(a,b);
}

// FFT-512: 64-thread block, x[n1] = x[n1*64+t] entry, x[q2] = X[q2*64+t] exit.
template<int DIR>
__device__ __forceinline__ void fft512_core(float2 x[8], float2* s, int t) {
    dft8<DIR>(x);
    float2 w = g_tw[t];
    if (DIR < 0) w.y = -w.y;
    float2 cw = w;
#pragma unroll
    for (int k1 = 1; k1 < 8; k1++) { x[k1] = cmul(x[k1], cw); cw = cmul(cw, w); }
    {
        float4* s4 = reinterpret_cast<float4*>(s + (size_t)t * EX1S);
        s4[0] = make_float4(x[0].x, x[0].y, x[1].x, x[1].y);
        s4[1] = make_float4(x[2].x, x[2].y, x[3].x, x[3].y);
        s4[2] = make_float4(x[4].x, x[4].y, x[5].x, x[5].y);
        s4[3] = make_float4(x[6].x, x[6].y, x[7].x, x[7].y);
    }
    __syncthreads();
    int k1 = t >> 3, m2 = t & 7;
#pragma unroll
    for (int m1 = 0; m1 < 8; m1++) x[m1] = s[(m1 * 8 + m2) * EX1S + k1];
    __syncthreads();
    dft8<DIR>(x);
    w = g_tw[8 * m2];
    if (DIR < 0) w.y = -w.y;
    cw = w;
#pragma unroll
    for (int q1 = 1; q1 < 8; q1++) { x[q1] = cmul(x[q1], cw); cw = cmul(cw, w); }
#pragma unroll
    for (int q1 = 0; q1 < 8; q1++) s[m2 * P512B + q1 * 8 + k1] = x[q1];
    __syncthreads();
    int k1c = t & 7, q1c = t >> 3;
#pragma unroll
    for (int m = 0; m < 8; m++) x[m] = s[m * P512B + q1c * 8 + k1c];
    __syncthreads();
    dft8<DIR>(x);   // output: X[q2*64 + q1c*8 + k1c] = X[q2*64 + t]
}

// Forward FFT-256 (DIF form): entry x[n1] = col[n1*16+q] natural.
// Exit x[p] = X[BR16[p]*16 + q]  (BR slot order; consumers slot-aligned).
template<int DIR>
__device__ __forceinline__ void fft256_dif(float2 x[16], float2* E, int c, int q) {
    dif16<DIR>(x);                      // x[p] = partial[BR16[p]]
    float2 w = g_tw[2 * q];
    if (DIR < 0) w.y = -w.y;
    float2 cw = make_float2(1.f, 0.f);
    {
        float4* e4 = reinterpret_cast<float4*>(E + c * E2C + q * E2S);
#pragma unroll
        for (int p = 0; p < 8; p++) {   // k1 = 2p, 2p+1 natural order
            float2 va = cmul(x[BR16[2*p]],   cw); cw = cmul(cw, w);
            float2 vb = cmul(x[BR16[2*p+1]], cw); cw = cmul(cw, w);
            e4[p] = make_float4(va.x, va.y, vb.x, vb.y);
        }
    }
    __syncwarp();
#pragma unroll
    for (int n2 = 0; n2 < 16; n2++) x[n2] = E[c * E2C + n2 * E2S + q];
    __syncwarp();
    dif16<DIR>(x);                      // x[p] = X[BR16[p]*16 + q]
}

// Inverse FFT-256 consuming BR-slot input: entry x[p] = P[BR16[p]*16 + q].
// Exit x[p] = z[BR16[p]*16 + q] (spatial rows, BR slot order).
__device__ __forceinline__ void fft256_inv_br(float2 x[16], float2* E, int c, int q) {
    dit16<-1>(x);                       // inverse DFT over high digit -> natural r
    float2 w = g_tw[2 * q];
    w.y = -w.y;                         // conj for inverse
    float2 cw = make_float2(1.f, 0.f);
    {
        float4* e4 = reinterpret_cast<float4*>(E + c * E2C + q * E2S);
#pragma unroll
        for (int p = 0; p < 8; p++) {   // r = 2p, 2p+1 natural
            float2 va = cmul(x[2*p],   cw); cw = cmul(cw, w);
            float2 vb = cmul(x[2*p+1], cw); cw = cmul(cw, w);
            e4[p] = make_float4(va.x, va.y, vb.x, vb.y);
        }
    }
    __syncwarp();
#pragma unroll
    for (int n = 0; n < 16; n++) x[n] = E[c * E2C + n * E2S + q];
    __syncwarp();
    dif16<-1>(x);                       // x[p] = z[BR16[p]*16 + role]
}

// Stage 1: one row per 64-thread block: pack z=u+ik, FFT-512, store fp16.
__global__ void __launch_bounds__(64) stage1_kernel(const float* __restrict__ u,
                                                    const float* __restrict__ kin) {
    __shared__ __align__(16) float2 sm[SROW];
    int t = threadIdx.x;
    int row = blockIdx.x;               // img*251 + h
    size_t ibase = (size_t)row * WW;
    float2 x[8];
#pragma unroll
    for (int a = 0; a < 8; a++) {
        int n = a * 64 + t;
        float ur = 0.f, kr = 0.f;
        if (n < WW) { ur = u[ibase + n]; kr = kin[ibase + n]; }
        x[a] = make_float2(ur, kr);
    }
    fft512_core<1>(x, sm, t);
    size_t obase = (size_t)row * ZP;
#pragma unroll
    for (int q2 = 0; q2 < 8; q2++)
        g_Zh[obase + q2 * 64 + t] = __float22half2_rn(x[q2]);
}

// Stage 2: per (image, 16-col tile). Smem: E (exchange, aliased with the
// Ms staging/out tile) | T2h | Ps. 70656 B -> 3 blocks/SM; launch_bounds
// (256,3) caps regs at 85 (in-place dft16 fits without spills).
__global__ void __launch_bounds__(256, 3) stage2_kernel() {
    extern __shared__ char dsmc[];
    float2*  E   = reinterpret_cast<float2*>(dsmc);            // 36864 B
    __half2* Ms  = reinterpret_cast<__half2*>(dsmc);           // alias of E
    __half2* T2h = reinterpret_cast<__half2*>(dsmc + 36864);   // 16384 B
    __half2* Ps  = reinterpret_cast<__half2*>(dsmc + 53248);   // 17408 B
    const int t = threadIdx.x;
    const int c = t >> 4;
    const int q = t & 15;
    const int img = blockIdx.y;
    const int j0  = blockIdx.x * 16;
    const size_t zbase = (size_t)img * HH * ZP;
    const float CS   = 0.25f * 2.1073424255447017e-08f;  // 0.25 * 2^-25.5
    const float T2S  = CS * 4096.0f;                      // T2 pre-scale
    const float CS2  = CS * 64.0f;                        // product pre-scale
    const float T2D  = 1.0f / 64.0f;                      // 64/4096
    const __half2 hz = __float22half2_rn(make_float2(0.f, 0.f));
    float2 x[16];

    // ---- stage BOTH tiles (raw half2), loads issued back-to-back ----
    int jm = (512 - (j0 + q)) & 511;
#pragma unroll
    for (int m = 0; m < 16; m++) {
        int h = c + 16 * m;
        Ms[h * 17 + q] = (h < HH) ? g_Zh[zbase + (size_t)h * ZP + jm] : hz;
        Ps[h * 17 + q] = (h < HH) ? g_Zh[zbase + (size_t)h * ZP + j0 + q] : hz;
    }
    __syncthreads();   // sync 1: staging complete

    // ---- mirror tile transposed read (conj), then free Ms region for E ----
#pragma unroll
    for (int n1 = 0; n1 < 16; n1++) {
        float2 v = __half22float2(Ms[(n1 * 16 + q) * 17 + c]);
        x[n1] = make_float2(v.x, -v.y);
    }
    __syncthreads();   // sync 2: all warps done reading Ms before E writes
    fft256_dif<1>(x, E, c, q);          // x[p] = Bbar at BR slot p

    // T2h = T2S * i * Bbar^2  (slot-aligned; same thread writes & reads)
#pragma unroll
    for (int p = 0; p < 16; p++) {
        float2 pr = cmul(x[p], x[p]);
        T2h[c * 256 + p * 16 + q] =
            __float22half2_rn(make_float2(-T2S * pr.y, T2S * pr.x));
    }

    // ---- primary tile (Ps region stable since sync 1) ----
#pragma unroll
    for (int n1 = 0; n1 < 16; n1++)
        x[n1] = __half22float2(Ps[(n1 * 16 + q) * 17 + c]);
    fft256_dif<1>(x, E, c, q);          // x[p] = A2 at BR slot p

    // ---- product (x64 pre-scale for fp16 storage) ----
#pragma unroll
    for (int p = 0; p < 16; p++) {
        float2 pr = cmul(x[p], x[p]);
        float2 t2 = __half22float2(T2h[c * 256 + p * 16 + q]);
        x[p] = make_float2(CS2 * pr.y + t2.x * T2D,
                           -CS2 * pr.x + t2.y * T2D);
    }

    // ---- inverse column FFT (BR-slot input) ----
    fft256_inv_br(x, E, c, q);          // x[p] = z[BR16[p]*16 + q]

    // ---- stage out into Ms region (E fully consumed after sync 3) ----
    __syncthreads();   // sync 3
#pragma unroll
    for (int p = 0; p < 16; p++)
        Ms[(BR16[p] * 16 + q) * 17 + c] = __float22half2_rn(x[p]);
    __syncthreads();   // sync 4: out tile complete
    if (j0 + q < NJ) {
        size_t pbase = (size_t)img * HH * WPAD + j0 + q;
#pragma unroll
        for (int m = 0; m < 16; m++) {
            int h = c + 16 * m;
            if (h < HH) g_Ph[pbase + (size_t)h * WPAD] = Ms[h * 17 + q];
        }
    }
}

// Stage 3: TWO rows per 64-thread block. x = P1ext + i*P2ext, one inverse
// FFT-512, y1 = Re -> row0, y2 = Im -> row1. Exact (linearity).
__global__ void __launch_bounds__(64) stage3_kernel(float* __restrict__ out) {
    __shared__ __align__(16) float2 sm[SROW];
    int t = threadIdx.x;
    int row0 = blockIdx.x * 2;
    size_t ib1 = (size_t)row0 * WPAD;
    size_t ib2 = ib1 + WPAD;
    float2 x[8];
#pragma unroll
    for (int a = 0; a < 8; a++) {
        int n = a * 64 + t;
        float2 p1, p2;
        if (n <= 256) {
            p1 = __half22float2(g_Ph[ib1 + n]);
            p2 = __half22float2(g_Ph[ib2 + n]);
        } else {
            float2 v1 = __half22float2(g_Ph[ib1 + 512 - n]);
            float2 v2 = __half22float2(g_Ph[ib2 + 512 - n]);
            p1 = make_float2(v1.x, -v1.y);
            p2 = make_float2(v2.x, -v2.y);
        }
        x[a] = make_float2(p1.x - p2.y, p1.y + p2.x);
    }
    fft512_core<-1>(x, sm, t);
    size_t ob1 = (size_t)row0 * WW;
    size_t ob2 = ob1 + WW;
    const float OD = 1.0f / 64.0f;
#pragma unroll
    for (int q2 = 0; q2 < 8; q2++) {
        int n = q2 * 64 + t;
        if (n < WW) {
            out[ob1 + n] = x[q2].x * OD;
            out[ob2 + n] = x[q2].y * OD;
        }
    }
}

extern "C" void kernel_launch(void* const* d_in, const int* in_sizes, int n_in,
                              void* d_out, int out_size) {
    const float* u  = (const float*)d_in[0];
    const float* kk = (const float*)d_in[1];
    float* out = (float*)d_out;

    cudaFuncSetAttribute(stage2_kernel,
                         cudaFuncAttributeMaxDynamicSharedMemorySize, 70656);

    init_tw_kernel<<<1, 512>>>();
    stage1_kernel<<<IMGS * HH, 64>>>(u, kk);         // 64256 rows
    stage2_kernel<<<dim3(17, IMGS), 256, 70656>>>(); // 17 col-tiles x 256 images
    stage3_kernel<<<IMGS * HH / 2, 64>>>(out);       // 32128 row-pairs
}

// round 11
// speedup vs baseline: 1.0157x; 1.0157x over previous
#include <cuda_runtime.h>
#include <cuda_fp16.h>

// y = irfft2(rfft2(pad(u)) * rfft2(pad(k)), ortho) cropped.
// (4,64,251,509) fp32 -> 256 images 251x509, pad to 256x512.
// Pack z = u + i*k; with Z2 = FFT2(z):
//   P = U2*K2 = -0.25i*(Z2[ky,kx]^2 - conj(Z2[-ky,-kx])^2)
// conj(Z2[-ky,-kx]) = FFT_col(conj(Z[h,-kx])) -- conj-on-load, no gather.
// Combined ortho scale 2^-25.5 folded into the product.
// fp16 intermediates (tol 1e-3): g_Zh raw, g_Ph pre-scaled 2^6, T2 2^12.
// Stage2 dft16s are in-place DIF/DIT (bit-reversal = compile-time renaming)
// to cut register pressure -> 3 blocks/SM. Stage3 pairs 2 rows per IFFT.

#define IMGS 256
#define HH   251
#define WW   509
#define NJ   257
#define ZP   516   // half2 row stride of Z scratch
#define WPAD 260   // half2 row stride of product scratch
#define EX1S 10    // fft512 exchange-1 stride (16B aligned, conflict-free)
#define P512B 66   // fft512 exchange-2 stride (conflict-free both sides)
#define SROW 656   // smem float2 for fft512 (>= 64*10)
#define E2S  18    // fft256 exchange per-thread stride (float2)
#define E2C  288   // fft256 exchange per-column stride (float2) = 16*18

__device__ __half2 g_Zh[IMGS * HH * ZP];   // packed row spectra (fp16)
__device__ __half2 g_Ph[IMGS * HH * WPAD]; // product half-spectrum (fp16, x64)
__device__ float2  g_tw[512];              // tw[r] = exp(-2*pi*i*r/512)

__global__ void init_tw_kernel() {
    int r = threadIdx.x;
    double ang = -2.0 * 3.141592653589793238462643383279502884 * (double)r / 512.0;
    g_tw[r] = make_float2((float)cos(ang), (float)sin(ang));
}

__device__ __forceinline__ float2 cmul(float2 a, float2 b) {
    return make_float2(a.x*b.x - a.y*b.y, a.x*b.y + a.y*b.x);
}
__device__ __forceinline__ float2 cadd(float2 a, float2 b) { return make_float2(a.x+b.x, a.y+b.y); }
__device__ __forceinline__ float2 csub(float2 a, float2 b) { return make_float2(a.x-b.x, a.y-b.y); }
template<int DIR>
__device__ __forceinline__ float2 mulmi(float2 v) {   // * (-i) fwd, * (+i) inv
    return (DIR == 1) ? make_float2(v.y, -v.x) : make_float2(-v.y, v.x);
}

// bit-reverse of 4 bits (involution)
__device__ __constant__ const int BR16[16] =
    {0,8,4,12,2,10,6,14,1,9,5,13,3,11,7,15};

template<int DIR>
__device__ __forceinline__ void dft8(float2 x[8]) {
    const float C = 0.70710678118654752f;
    float2 t0 = cadd(x[0], x[4]), t4 = csub(x[0], x[4]);
    float2 t1 = cadd(x[1], x[5]), t5 = csub(x[1], x[5]);
    float2 t2 = cadd(x[2], x[6]), t6 = csub(x[2], x[6]);
    float2 t3 = cadd(x[3], x[7]), t7 = csub(x[3], x[7]);
    t5 = cmul(t5, make_float2(C, -DIR * C));
    t6 = mulmi<DIR>(t6);
    t7 = cmul(t7, make_float2(-C, -DIR * C));
    float2 p0 = cadd(t0, t2), q0 = csub(t0, t2);
    float2 p1 = cadd(t1, t3), q1 = mulmi<DIR>(csub(t1, t3));
    x[0] = cadd(p0, p1); x[4] = csub(p0, p1);
    x[2] = cadd(q0, q1); x[6] = csub(q0, q1);
    float2 r0 = cadd(t4, t6), s0 = csub(t4, t6);
    float2 r1 = cadd(t5, t7), s1 = mulmi<DIR>(csub(t5, t7));
    x[1] = cadd(r0, r1); x[5] = csub(r0, r1);
    x[3] = cadd(s0, s1); x[7] = csub(s0, s1);
}

// In-place DIF radix-2 DFT-16: natural input, output x[p] = X[BR16[p]].
template<int DIR>
__device__ __forceinline__ void dif16(float2 x[16]) {
    const float c1 = 0.92387953251128674f, s1 = 0.38268343236508978f;
    const float C = 0.70710678118654752f;
    const float2 W1 = make_float2(c1, -DIR*s1);
    const float2 W2 = make_float2(C,  -DIR*C);
    const float2 W3 = make_float2(s1, -DIR*c1);
    const float2 W5 = make_float2(-s1,-DIR*c1);
    const float2 W6 = make_float2(-C, -DIR*C);
    const float2 W7 = make_float2(-c1,-DIR*s1);
    float2 a, d;
    // half = 8, twiddles W16^j
    a=x[0]; d=csub(a,x[8]);  x[0]=cadd(a,x[8]);  x[8]=d;
    a=x[1]; d=csub(a,x[9]);  x[1]=cadd(a,x[9]);  x[9]=cmul(d,W1);
    a=x[2]; d=csub(a,x[10]); x[2]=cadd(a,x[10]); x[10]=cmul(d,W2);
    a=x[3]; d=csub(a,x[11]); x[3]=cadd(a,x[11]); x[11]=cmul(d,W3);
    a=x[4]; d=csub(a,x[12]); x[4]=cadd(a,x[12]); x[12]=mulmi<DIR>(d);
    a=x[5]; d=csub(a,x[13]); x[5]=cadd(a,x[13]); x[13]=cmul(d,W5);
    a=x[6]; d=csub(a,x[14]); x[6]=cadd(a,x[14]); x[14]=cmul(d,W6);
    a=x[7]; d=csub(a,x[15]); x[7]=cadd(a,x[15]); x[15]=cmul(d,W7);
    // half = 4, twiddles W8^j = {1, W2, -i, W6}
#pragma unroll
    for (int b0 = 0; b0 < 16; b0 += 8) {
        a=x[b0+0]; d=csub(a,x[b0+4]); x[b0+0]=cadd(a,x[b0+4]); x[b0+4]=d;
        a=x[b0+1]; d=csub(a,x[b0+5]); x[b0+1]=cadd(a,x[b0+5]); x[b0+5]=cmul(d,W2);
        a=x[b0+2]; d=csub(a,x[b0+6]); x[b0+2]=cadd(a,x[b0+6]); x[b0+6]=mulmi<DIR>(d);
        a=x[b0+3]; d=csub(a,x[b0+7]); x[b0+3]=cadd(a,x[b0+7]); x[b0+7]=cmul(d,W6);
    }
    // half = 2, twiddles {1, -i}
#pragma unroll
    for (int b0 = 0; b0 < 16; b0 += 4) {
        a=x[b0+0]; d=csub(a,x[b0+2]); x[b0+0]=cadd(a,x[b0+2]); x[b0+2]=d;
        a=x[b0+1]; d=csub(a,x[b0+3]); x[b0+1]=cadd(a,x[b0+3]); x[b0+3]=mulmi<DIR>(d);
    }
    // half = 1
#pragma unroll
    for (int b0 = 0; b0 < 16; b0 += 2) {
        a=x[b0]; float2 b=x[b0+1];
        x[b0]=cadd(a,b); x[b0+1]=csub(a,b);
    }
}

// In-place DIT radix-2 DFT-16: input x[p] = data[BR16[p]], natural output.
template<int DIR>
__device__ __forceinline__ void dit16(float2 x[16]) {
    const float c1 = 0.92387953251128674f, s1 = 0.38268343236508978f;
    const float C = 0.70710678118654752f;
    const float2 W1 = make_float2(c1, -DIR*s1);
    const float2 W2 = make_float2(C,  -DIR*C);
    const float2 W3 = make_float2(s1, -DIR*c1);
    const float2 W5 = make_float2(-s1,-DIR*c1);
    const float2 W6 = make_float2(-C, -DIR*C);
    const float2 W7 = make_float2(-c1,-DIR*s1);
    float2 a, b;
    // half = 1
#pragma unroll
    for (int b0 = 0; b0 < 16; b0 += 2) {
        a=x[b0]; b=x[b0+1];
        x[b0]=cadd(a,b); x[b0+1]=csub(a,b);
    }
    // half = 2, twiddles {1, -i}
#pragma unroll
    for (int b0 = 0; b0 < 16; b0 += 4) {
        a=x[b0+0]; b=x[b0+2];            x[b0+0]=cadd(a,b); x[b0+2]=csub(a,b);
        a=x[b0+1]; b=mulmi<DIR>(x[b0+3]); x[b0+1]=cadd(a,b); x[b0+3]=csub(a,b);
    }
    // half = 4, twiddles {1, W2, -i, W6}
#pragma unroll
    for (int b0 = 0; b0 < 16; b0 += 8) {
        a=x[b0+0]; b=x[b0+4];             x[b0+0]=cadd(a,b); x[b0+4]=csub(a,b);
        a=x[b0+1]; b=cmul(x[b0+5],W2);    x[b0+1]=cadd(a,b); x[b0+5]=csub(a,b);
        a=x[b0+2]; b=mulmi<DIR>(x[b0+6]); x[b0+2]=cadd(a,b); x[b0+6]=csub(a,b);
        a=x[b0+3]; b=cmul(x[b0+7],W6);    x[b0+3]=cadd(a,b); x[b0+7]=csub(a,b);
    }
    // half = 8, twiddles W16^j
    a=x[0]; b=x[8];            x[0]=cadd(a,b); x[8]=csub(a,b);
    a=x[1]; b=cmul(x[9],W1);   x[1]=cadd(a,b); x[9]=csub(a,b);
    a=x[2]; b=cmul(x[10],W2);  x[2]=cadd(a,b); x[10]=csub(a,b);
    a=x[3]; b=cmul(x[11],W3);  x[3]=cadd(a,b); x[11]=csub(a,b);
    a=x[4]; b=mulmi<DIR>(x[12]); x[4]=cadd(a,b); x[12]=csub(a,b);
    a=x[5]; b=cmul(x[13],W5);  x[5]=cadd(a,b); x[13]=csub(a,b);
    a=x[6]; b=cmul(x[14],W6);  x[6]=cadd(a,b); x[14]=csub(a,b);
    a=x[7]; b=cmul(x[15],W7);  x[7]=cadd(a,b); x[15]=csub(a,b);
}

// FFT-512: 64-thread block, x[n1] = x[n1*64+t] entry, x[q2] = X[q2*64+t] exit.
template<int DIR>
__device__ __forceinline__ void fft512_core(float2 x[8], float2* s, int t) {
    dft8<DIR>(x);
    float2 w = g_tw[t];
    if (DIR < 0) w.y = -w.y;
    float2 cw = w;
#pragma unroll
    for (int k1 = 1; k1 < 8; k1++) { x[k1] = cmul(x[k1], cw); cw = cmul(cw, w); }
    {
        float4* s4 = reinterpret_cast<float4*>(s + (size_t)t * EX1S);
        s4[0] = make_float4(x[0].x, x[0].y, x[1].x, x[1].y);
        s4[1] = make_float4(x[2].x, x[2].y, x[3].x, x[3].y);
        s4[2] = make_float4(x[4].x, x[4].y, x[5].x, x[5].y);
        s4[3] = make_float4(x[6].x, x[6].y, x[7].x, x[7].y);
    }
    __syncthreads();
    int k1 = t >> 3, m2 = t & 7;
#pragma unroll
    for (int m1 = 0; m1 < 8; m1++) x[m1] = s[(m1 * 8 + m2) * EX1S + k1];
    __syncthreads();
    dft8<DIR>(x);
    w = g_tw[8 * m2];
    if (DIR < 0) w.y = -w.y;
    cw = w;
#pragma unroll
    for (int q1 = 1; q1 < 8; q1++) { x[q1] = cmul(x[q1], cw); cw = cmul(cw, w); }
#pragma unroll
    for (int q1 = 0; q1 < 8; q1++) s[m2 * P512B + q1 * 8 + k1] = x[q1];
    __syncthreads();
    int k1c = t & 7, q1c = t >> 3;
#pragma unroll
    for (int m = 0; m < 8; m++) x[m] = s[m * P512B + q1c * 8 + k1c];
    __syncthreads();
    dft8<DIR>(x);   // output: X[q2*64 + q1c*8 + k1c] = X[q2*64 + t]
}

// Forward FFT-256 (DIF form): entry x[n1] = col[n1*16+q] natural.
// Exit x[p] = X[BR16[p]*16 + q]  (BR slot order; consumers slot-aligned).
template<int DIR>
__device__ __forceinline__ void fft256_dif(float2 x[16], float2* E, int c, int q) {
    dif16<DIR>(x);                      // x[p] = partial[BR16[p]]
    float2 w = g_tw[2 * q];
    if (DIR < 0) w.y = -w.y;
    float2 cw = make_float2(1.f, 0.f);
    {
        float4* e4 = reinterpret_cast<float4*>(E + c * E2C + q * E2S);
#pragma unroll
        for (int p = 0; p < 8; p++) {   // k1 = 2p, 2p+1 natural order
            float2 va = cmul(x[BR16[2*p]],   cw); cw = cmul(cw, w);
            float2 vb = cmul(x[BR16[2*p+1]], cw); cw = cmul(cw, w);
            e4[p] = make_float4(va.x, va.y, vb.x, vb.y);
        }
    }
    __syncwarp();
#pragma unroll
    for (int n2 = 0; n2 < 16; n2++) x[n2] = E[c * E2C + n2 * E2S + q];
    __syncwarp();
    dif16<DIR>(x);                      // x[p] = X[BR16[p]*16 + q]
}

// Inverse FFT-256 consuming BR-slot input: entry x[p] = P[BR16[p]*16 + q].
// Exit x[p] = z[BR16[p]*16 + q] (spatial rows, BR slot order).
__device__ __forceinline__ void fft256_inv_br(float2 x[16], float2* E, int c, int q) {
    dit16<-1>(x);                       // inverse DFT over high digit -> natural r
    float2 w = g_tw[2 * q];
    w.y = -w.y;                         // conj for inverse
    float2 cw = make_float2(1.f, 0.f);
    {
        float4* e4 = reinterpret_cast<float4*>(E + c * E2C + q * E2S);
#pragma unroll
        for (int p = 0; p < 8; p++) {   // r = 2p, 2p+1 natural
            float2 va = cmul(x[2*p],   cw); cw = cmul(cw, w);
            float2 vb = cmul(x[2*p+1], cw); cw = cmul(cw, w);
            e4[p] = make_float4(va.x, va.y, vb.x, vb.y);
        }
    }
    __syncwarp();
#pragma unroll
    for (int n = 0; n < 16; n++) x[n] = E[c * E2C + n * E2S + q];
    __syncwarp();
    dif16<-1>(x);                       // x[p] = z[BR16[p]*16 + role]
}

// Stage 1: one row per 64-thread block: pack z=u+ik, FFT-512, store fp16.
__global__ void __launch_bounds__(64) stage1_kernel(const float* __restrict__ u,
                                                    const float* __restrict__ kin) {
    __shared__ __align__(16) float2 sm[SROW];
    int t = threadIdx.x;
    int row = blockIdx.x;               // img*251 + h
    size_t ibase = (size_t)row * WW;
    float2 x[8];
#pragma unroll
    for (int a = 0; a < 8; a++) {
        int n = a * 64 + t;
        float ur = 0.f, kr = 0.f;
        if (n < WW) { ur = u[ibase + n]; kr = kin[ibase + n]; }
        x[a] = make_float2(ur, kr);
    }
    fft512_core<1>(x, sm, t);
    size_t obase = (size_t)row * ZP;
#pragma unroll
    for (int q2 = 0; q2 < 8; q2++)
        g_Zh[obase + q2 * 64 + t] = __float22half2_rn(x[q2]);
}

// Stage 2: per (image, 16-col tile). Smem: E (exchange, aliased with the
// Ms staging/out tile) | T2h | Ps. 70656 B -> 3 blocks/SM; launch_bounds
// (256,3) caps regs at 85 (in-place dft16 fits without spills).
__global__ void __launch_bounds__(256, 3) stage2_kernel() {
    extern __shared__ char dsmc[];
    float2*  E   = reinterpret_cast<float2*>(dsmc);            // 36864 B
    __half2* Ms  = reinterpret_cast<__half2*>(dsmc);           // alias of E
    __half2* T2h = reinterpret_cast<__half2*>(dsmc + 36864);   // 16384 B
    __half2* Ps  = reinterpret_cast<__half2*>(dsmc + 53248);   // 17408 B
    const int t = threadIdx.x;
    const int c = t >> 4;
    const int q = t & 15;
    const int img = blockIdx.y;
    const int j0  = blockIdx.x * 16;
    const size_t zbase = (size_t)img * HH * ZP;
    const float CS   = 0.25f * 2.1073424255447017e-08f;  // 0.25 * 2^-25.5
    const float T2S  = CS * 4096.0f;                      // T2 pre-scale
    const float CS2  = CS * 64.0f;                        // product pre-scale
    const float T2D  = 1.0f / 64.0f;                      // 64/4096
    const __half2 hz = __float22half2_rn(make_float2(0.f, 0.f));
    float2 x[16];

    // ---- stage BOTH tiles (raw half2), loads issued back-to-back ----
    int jm = (512 - (j0 + q)) & 511;
#pragma unroll
    for (int m = 0; m < 16; m++) {
        int h = c + 16 * m;
        Ms[h * 17 + q] = (h < HH) ? g_Zh[zbase + (size_t)h * ZP + jm] : hz;
        Ps[h * 17 + q] = (h < HH) ? g_Zh[zbase + (size_t)h * ZP + j0 + q] : hz;
    }
    __syncthreads();   // sync 1: staging complete

    // ---- mirror tile transposed read (conj), then free Ms region for E ----
#pragma unroll
    for (int n1 = 0; n1 < 16; n1++) {
        float2 v = __half22float2(Ms[(n1 * 16 + q) * 17 + c]);
        x[n1] = make_float2(v.x, -v.y);
    }
    __syncthreads();   // sync 2: all warps done reading Ms before E writes
    fft256_dif<1>(x, E, c, q);          // x[p] = Bbar at BR slot p

    // T2h = T2S * i * Bbar^2  (slot-aligned; same thread writes & reads)
#pragma unroll
    for (int p = 0; p < 16; p++) {
        float2 pr = cmul(x[p], x[p]);
        T2h[c * 256 + p * 16 + q] =
            __float22half2_rn(make_float2(-T2S * pr.y, T2S * pr.x));
    }

    // ---- primary tile (Ps region stable since sync 1) ----
#pragma unroll
    for (int n1 = 0; n1 < 16; n1++)
        x[n1] = __half22float2(Ps[(n1 * 16 + q) * 17 + c]);
    fft256_dif<1>(x, E, c, q);          // x[p] = A2 at BR slot p

    // ---- product (x64 pre-scale for fp16 storage) ----
#pragma unroll
    for (int p = 0; p < 16; p++) {
        float2 pr = cmul(x[p], x[p]);
        float2 t2 = __half22float2(T2h[c * 256 + p * 16 + q]);
        x[p] = make_float2(CS2 * pr.y + t2.x * T2D,
                           -CS2 * pr.x + t2.y * T2D);
    }

    // ---- inverse column FFT (BR-slot input) ----
    fft256_inv_br(x, E, c, q);          // x[p] = z[BR16[p]*16 + q]

    // ---- stage out into Ms region (E fully consumed after sync 3) ----
    __syncthreads();   // sync 3
#pragma unroll
    for (int p = 0; p < 16; p++)
        Ms[(BR16[p] * 16 + q) * 17 + c] = __float22half2_rn(x[p]);
    __syncthreads();   // sync 4: out tile complete
    if (j0 + q < NJ) {
        size_t pbase = (size_t)img * HH * WPAD + j0 + q;
#pragma unroll
        for (int m = 0; m < 16; m++) {
            int h = c + 16 * m;
            if (h < HH) g_Ph[pbase + (size_t)h * WPAD] = Ms[h * 17 + q];
        }
    }
}

// Stage 3: TWO rows per 64-thread block. x = P1ext + i*P2ext, one inverse
// FFT-512, y1 = Re -> row0, y2 = Im -> row1. Exact (linearity).
__global__ void __launch_bounds__(64) stage3_kernel(float* __restrict__ out) {
    __shared__ __align__(16) float2 sm[SROW];
    int t = threadIdx.x;
    int row0 = blockIdx.x * 2;
    size_t ib1 = (size_t)row0 * WPAD;
    size_t ib2 = ib1 + WPAD;
    float2 x[8];
#pragma unroll
    for (int a = 0; a < 8; a++) {
        int n = a * 64 + t;
        float2 p1, p2;
        if (n <= 256) {
            p1 = __half22float2(g_Ph[ib1 + n]);
            p2 = __half22float2(g_Ph[ib2 + n]);
        } else {
            float2 v1 = __half22float2(g_Ph[ib1 + 512 - n]);
            float2 v2 = __half22float2(g_Ph[ib2 + 512 - n]);
            p1 = make_float2(v1.x, -v1.y);
            p2 = make_float2(v2.x, -v2.y);
        }
        x[a] = make_float2(p1.x - p2.y, p1.y + p2.x);
    }
    fft512_core<-1>(x, sm, t);
    size_t ob1 = (size_t)row0 * WW;
    size_t ob2 = ob1 + WW;
    const float OD = 1.0f / 64.0f;
#pragma unroll
    for (int q2 = 0; q2 < 8; q2++) {
        int n = q2 * 64 + t;
        if (n < WW) {
            out[ob1 + n] = x[q2].x * OD;
            out[ob2 + n] = x[q2].y * OD;
        }
    }
}

extern "C" void kernel_launch(void* const* d_in, const int* in_sizes, int n_in,
                              void* d_out, int out_size) {
    const float* u  = (const float*)d_in[0];
    const float* kk = (const float*)d_in[1];
    float* out = (float*)d_out;

    cudaFuncSetAttribute(stage2_kernel,
                         cudaFuncAttributeMaxDynamicSharedMemorySize, 70656);

    init_tw_kernel<<<1, 512>>>();
    stage1_kernel<<<IMGS * HH, 64>>>(u, kk);         // 64256 rows
    stage2_kernel<<<dim3(17, IMGS), 256, 70656>>>(); // 17 col-tiles x 256 images
    stage3_kernel<<<IMGS * HH / 2, 64>>>(out);       // 32128 row-pairs
}